// round 7
// baseline (speedup 1.0000x reference)
#include <cuda_runtime.h>
#include <cstdint>

// ---------------- config ----------------
#define CTAS        1024
#define THREADS     512              // 16 warps, 8 pairs
#define STAGE_ROWS  128
#define STAGE_BYTES 32768
#define RING        6
#define NSTAGES     8                // 1024 CTAs * 8 * 128 rows = 2^20

// smem: FB (plain tf32 W, 16 KB) + ring
#define FB_BYTES    16384
#define SMEM_X      FB_BYTES
#define SMEM_TOTAL  (FB_BYTES + RING * STAGE_BYTES)   // 212992

#define NROWS       (1 << 20)

// partial sums: sc[h][row]
__device__ float g_sc[2][NROWS];

// ---------------- math constants ----------------
#define C_SCALE_L2E  4.3280851227f   // 3 * log2(e)
#define C_CLAMP_L2E 14.4269504089f   // 10 * log2(e)
#define C_LN2        0.6931471806f

// ---------------- helpers ----------------
static __device__ __forceinline__ uint32_t smem_u32(const void* p) {
    uint32_t a;
    asm("{ .reg .u64 t; cvta.to.shared.u64 t, %1; cvt.u32.u64 %0, t; }"
        : "=r"(a) : "l"(p));
    return a;
}
static __device__ __forceinline__ void cp16(uint32_t s, const void* g) {
    asm volatile("cp.async.cg.shared.global [%0], [%1], 16;" :: "r"(s), "l"(g));
}
#define CP_COMMIT() asm volatile("cp.async.commit_group;" ::: "memory")
#define CP_WAIT(n)  asm volatile("cp.async.wait_group %0;" :: "n"(n) : "memory")

static __device__ __forceinline__ float exp2_fast(float x) {
    float r; asm("ex2.approx.ftz.f32 %0, %1;" : "=f"(r) : "f"(x)); return r;
}
static __device__ __forceinline__ float lg2_fast(float x) {
    float r; asm("lg2.approx.f32 %0, %1;" : "=f"(r) : "f"(x)); return r;
}
static __device__ __forceinline__ float rcp_fast(float x) {
    float r; asm("rcp.approx.ftz.f32 %0, %1;" : "=f"(r) : "f"(x)); return r;
}
static __device__ __forceinline__ uint32_t f2tf32(float v) {
    uint32_t r; asm("cvt.rna.tf32.f32 %0, %1;" : "=r"(r) : "f"(v)); return r;
}

// mma.sync m16n8k8 tf32
static __device__ __forceinline__ void mma_tf32(
    float* d, uint32_t a0, uint32_t a1, uint32_t a2, uint32_t a3,
    uint32_t b0, uint32_t b1) {
    asm volatile(
        "mma.sync.aligned.m16n8k8.row.col.f32.tf32.tf32.f32 "
        "{%0,%1,%2,%3}, {%4,%5,%6,%7}, {%8,%9}, {%0,%1,%2,%3};"
        : "+f"(d[0]), "+f"(d[1]), "+f"(d[2]), "+f"(d[3])
        : "r"(a0), "r"(a1), "r"(a2), "r"(a3), "r"(b0), "r"(b1));
}

static __device__ __forceinline__ float expv(float z) {
    float w = fminf(fmaxf(z * C_SCALE_L2E, -C_CLAMP_L2E), C_CLAMP_L2E);
    return exp2_fast(w);
}
// mish(ln s): e^(ln s) == s exactly -> tanh(softplus) = ((1+s)^2-1)/((1+s)^2+1)
static __device__ __forceinline__ float mish_of_ln(float s) {
    float lse = C_LN2 * lg2_fast(s);
    float up  = s + 1.0f;
    float q   = up * up;
    return lse * (q - 1.0f) * rcp_fast(q + 1.0f);
}

// issue one 128-row stage (32 KB contiguous): 8 cp16 per thread (512 thr)
// dst swizzle: within-row 16B-chunk c -> c ^ ((row&3)<<2)
static __device__ __forceinline__ void load_stage(
    uint32_t dst_base, const float* __restrict__ src, int tid) {
#pragma unroll
    for (int i = 0; i < 4; i++) {
        int idx = i * THREADS + tid;        // 2048 16B-chunks
        int r = idx >> 4, c = idx & 15;
        cp16(dst_base + (uint32_t)(r * 256 + ((c ^ ((r & 3) << 2)) << 4)),
             src + (size_t)idx * 4);
    }
}

// ---------------- kernel 1: GEMM + partial sum-exp ----------------
__global__ void __launch_bounds__(THREADS, 1) k1_gemm_partial(
    const float* __restrict__ x, const float* __restrict__ W) {
    extern __shared__ char smem[];
    const uint32_t sb = smem_u32(smem);
    const int tid  = threadIdx.x;
    const int lane = tid & 31;
    const int w    = tid >> 5;
    const int h    = w & 1;              // column half: cols 32h..32h+31
    const int pair = w >> 1;             // 0..7 -> rows 16*pair..16*pair+15
    const int g    = lane >> 2;          // 0..7
    const int t    = lane & 3;           // 0..3

    const size_t crow0 = (size_t)blockIdx.x * (NSTAGES * STAGE_ROWS);

    // ---- prologue loads first: start DRAM early (stages 0..RING-2) ----
#pragma unroll
    for (int s = 0; s < RING - 1; s++) {
        load_stage(sb + SMEM_X + (uint32_t)s * STAGE_BYTES,
                   x + (crow0 + (size_t)s * STAGE_ROWS) * 64, tid);
        CP_COMMIT();
    }

    // ---- FB: W as plain tf32 [n][k] (one-time) ----
    uint32_t* FB = reinterpret_cast<uint32_t*>(smem);
#pragma unroll
    for (int i = 0; i < 8; i++)
        FB[i * THREADS + tid] = f2tf32(W[i * THREADS + tid]);
    __syncthreads();

    // ---- permanent B fragments (permuted-K mapping) ----
    // mma kb = 2*seg+m uses k-slots: slot t -> col 16seg+4t+2m, slot t+4 -> col+1
    uint32_t b[8][4][2];                 // [kb][nb][b0,b1]
#pragma unroll
    for (int seg = 0; seg < 4; seg++)
#pragma unroll
        for (int m = 0; m < 2; m++)
#pragma unroll
            for (int nb = 0; nb < 4; nb++) {
                int n = (4 * h + nb) * 8 + g;
                int col = 16 * seg + 4 * t + 2 * m;
                b[2 * seg + m][nb][0] = FB[n * 64 + col];
                b[2 * seg + m][nb][1] = FB[n * 64 + col + 1];
            }

    const uint32_t rowlo = (uint32_t)(16 * pair + g);      // local row (a0/a2)
    const uint32_t rowhi = rowlo + 8;                      // local row (a1/a3)
    const uint32_t swlo = (uint32_t)(rowlo * 256);
    const uint32_t swhi = (uint32_t)(rowhi * 256);
    const uint32_t cxor = (uint32_t)(((rowlo & 3) << 2));  // same for rowhi (&3 equal)

    for (int u = 0; u < NSTAGES; u++) {
        CP_WAIT(RING - 2);               // stage u resident (in-order groups)
        __syncthreads();

        const char* As = smem + SMEM_X + (size_t)(u % RING) * STAGE_BYTES;

        float acc[4][4];
#pragma unroll
        for (int nb = 0; nb < 4; nb++)
#pragma unroll
            for (int q = 0; q < 4; q++) acc[nb][q] = 0.0f;

#pragma unroll
        for (int seg = 0; seg < 4; seg++) {
            const uint32_t ch = (uint32_t)((4 * seg + t) ^ cxor) << 4;
            uint4 vlo = *reinterpret_cast<const uint4*>(As + swlo + ch);
            uint4 vhi = *reinterpret_cast<const uint4*>(As + swhi + ch);
            // kb = 2*seg  : slots (t, t+4) = cols (.. +0, .. +1) -> (v.x, v.y)
#pragma unroll
            for (int nb = 0; nb < 4; nb++)
                mma_tf32(acc[nb], vlo.x, vhi.x, vlo.y, vhi.y,
                         b[2 * seg][nb][0], b[2 * seg][nb][1]);
            // kb = 2*seg+1: cols (+2, +3) -> (v.z, v.w)
#pragma unroll
            for (int nb = 0; nb < 4; nb++)
                mma_tf32(acc[nb], vlo.z, vhi.z, vlo.w, vhi.w,
                         b[2 * seg + 1][nb][0], b[2 * seg + 1][nb][1]);
        }

        // ---- partial sum of exp over this warp's 32 columns ----
        float sl = 0.0f, sh = 0.0f;
#pragma unroll
        for (int nb = 0; nb < 4; nb++) {
            sl += expv(acc[nb][0]) + expv(acc[nb][1]);
            sh += expv(acc[nb][2]) + expv(acc[nb][3]);
        }
        sl += __shfl_xor_sync(0xFFFFFFFF, sl, 1);
        sl += __shfl_xor_sync(0xFFFFFFFF, sl, 2);
        sh += __shfl_xor_sync(0xFFFFFFFF, sh, 1);
        sh += __shfl_xor_sync(0xFFFFFFFF, sh, 2);
        if (t == 0) {
            size_t row = crow0 + (size_t)u * STAGE_ROWS + rowlo;
            g_sc[h][row]     = sl;
            g_sc[h][row + 8] = sh;
        }

        // ---- issue stage u+RING-1 into the slot just freed ----
        if (u + RING - 1 < NSTAGES)
            load_stage(sb + SMEM_X + (uint32_t)((u + RING - 1) % RING) * STAGE_BYTES,
                       x + (crow0 + (size_t)(u + RING - 1) * STAGE_ROWS) * 64, tid);
        CP_COMMIT();                     // uniform group accounting (empty ok)
    }
}

// ---------------- kernel 2: combine halves + mish ----------------
__global__ void __launch_bounds__(512, 2) k2_combine(float* __restrict__ out) {
    int i = blockIdx.x * 512 + threadIdx.x;
    float s = g_sc[0][i] + g_sc[1][i];
    out[i] = mish_of_ln(s);
}

// ---------------- launch ----------------
extern "C" void kernel_launch(void* const* d_in, const int* in_sizes, int n_in,
                              void* d_out, int out_size) {
    (void)in_sizes; (void)n_in; (void)out_size;
    const float* x = (const float*)d_in[0];
    const float* W = (const float*)d_in[1];
    float* out = (float*)d_out;

    cudaFuncSetAttribute(k1_gemm_partial,
                         cudaFuncAttributeMaxDynamicSharedMemorySize, SMEM_TOTAL);
    k1_gemm_partial<<<CTAS, THREADS, SMEM_TOTAL>>>(x, W);
    k2_combine<<<NROWS / 512, 512>>>(out);
}